// round 14
// baseline (speedup 1.0000x reference)
#include <cuda_runtime.h>
#include <cuda_fp16.h>
#include <cstdint>

#define HEAD_NUM 8
#define DIM_QK 64
#define DIM_V 64
#define SPAN 64
#define STRIDE 4
#define R_SPAN 16

#define BATCH 2
#define MAX_LQ 4096
#define MAX_LKV 1024
#define DMODEL 512
#define GK 512           // single-rounded fp16 GEMM
#define CHUNKS 8         // GK / 64
#define WSTRIDE (DMODEL * GK)

// ---------------------------------------------------------------------------
// Scratch (no cudaMalloc allowed)
// ---------------------------------------------------------------------------
__device__ __align__(16) __half g_Ab[BATCH * MAX_LQ * GK];    // q-act fp16, then ctx fp16
__device__ __align__(16) __half g_Kb[BATCH * MAX_LKV * GK];   // k-act fp16
__device__ __align__(16) __half g_Vb[BATCH * MAX_LKV * GK];   // v-act fp16
__device__ __align__(16) __half g_Wb4[4 * WSTRIDE];           // 4 weights (transposed) fp16
__device__ __align__(16) __half g_Qh[BATCH * MAX_LQ * DMODEL];
__device__ __align__(16) __half g_Kh[BATCH * MAX_LKV * DMODEL];
__device__ __align__(16) __half g_Vh[BATCH * MAX_LKV * DMODEL];

// ---------------------------------------------------------------------------
// Baseline-target PTX helpers
// ---------------------------------------------------------------------------
__device__ __forceinline__ uint32_t smem_u32(const void* p) {
    uint32_t a;
    asm("{ .reg .u64 t; cvta.to.shared.u64 t, %1; cvt.u32.u64 %0, t; }" : "=r"(a) : "l"(p));
    return a;
}
__device__ __forceinline__ void cp_async16(uint32_t saddr, const void* gaddr) {
    asm volatile("cp.async.cg.shared.global [%0], [%1], 16;" :: "r"(saddr), "l"(gaddr));
}
__device__ __forceinline__ void cp_commit() { asm volatile("cp.async.commit_group;" ::: "memory"); }
__device__ __forceinline__ void cp_wait1() { asm volatile("cp.async.wait_group 1;" ::: "memory"); }
__device__ __forceinline__ void cp_wait0() { asm volatile("cp.async.wait_group 0;" ::: "memory"); }
__device__ __forceinline__ void ldm_x4(uint32_t* r, uint32_t addr) {
    asm volatile("ldmatrix.sync.aligned.m8n8.x4.shared.b16 {%0,%1,%2,%3}, [%4];"
                 : "=r"(r[0]), "=r"(r[1]), "=r"(r[2]), "=r"(r[3]) : "r"(addr));
}
__device__ __forceinline__ void ldm_x2(uint32_t* r, uint32_t addr) {
    asm volatile("ldmatrix.sync.aligned.m8n8.x2.shared.b16 {%0,%1}, [%2];"
                 : "=r"(r[0]), "=r"(r[1]) : "r"(addr));
}
__device__ __forceinline__ void mma_f16(float* c, const uint32_t* a, const uint32_t* b) {
    asm volatile("mma.sync.aligned.m16n8k16.row.col.f32.f16.f16.f32 "
                 "{%0,%1,%2,%3}, {%4,%5,%6,%7}, {%8,%9}, {%0,%1,%2,%3};"
                 : "+f"(c[0]), "+f"(c[1]), "+f"(c[2]), "+f"(c[3])
                 : "r"(a[0]), "r"(a[1]), "r"(a[2]), "r"(a[3]), "r"(b[0]), "r"(b[1]));
}
__device__ __forceinline__ uint32_t sw128(uint32_t off) { return off ^ ((off >> 3) & 0x70); }

// ---------------------------------------------------------------------------
// GEMM tile worker: CTA 128x64, 8 warps (4x2), warp tile 32x32.
// 2-stage cp.async pipeline, safe ordering:
//   top sync -> issue(i+1) into buf^1 -> wait_group 1 -> compute(i)
// Stage = A 16KB + B 8KB = 24KB; total 48KB -> 3 CTAs/SM (regs capped 85).
// ---------------------------------------------------------------------------
#define STAGE_BYTES 24576u
#define GEMM_SMEM (2 * STAGE_BYTES)

__device__ __forceinline__ void issue_chunk(const __half* __restrict__ A,
                                            const __half* __restrict__ Bt,
                                            uint32_t sb, int row0, int col0,
                                            int chunk, int stage, int tid) {
    const int k0 = chunk * 64;
    const uint32_t aoff = stage * STAGE_BYTES;
    const uint32_t boff = aoff + 16384u;
    #pragma unroll
    for (int p = 0; p < 4; p++) {
        const int idx = tid + p * 256;        // A: 128 rows x 8 x 16B
        const int r = idx >> 3;
        const int c8 = idx & 7;
        const uint32_t sw = sw128((uint32_t)(r * 128 + c8 * 16));
        cp_async16(sb + aoff + sw, A + (size_t)(row0 + r) * GK + k0 + c8 * 8);
    }
    #pragma unroll
    for (int p = 0; p < 2; p++) {
        const int idx = tid + p * 256;        // B: 64 rows x 8 x 16B
        const int r = idx >> 3;
        const int c8 = idx & 7;
        const uint32_t sw = sw128((uint32_t)(r * 128 + c8 * 16));
        cp_async16(sb + boff + sw, Bt + (size_t)(col0 + r) * GK + k0 + c8 * 8);
    }
    cp_commit();
}

template <bool HOUT>
__device__ __forceinline__ void gemm_tile(const __half* __restrict__ A,
                                          const __half* __restrict__ Bt,
                                          void* __restrict__ Cp,
                                          int row0, int col0, uint32_t sb, int tid) {
    const int wid = tid >> 5, lane = tid & 31;
    const int warpM = wid >> 1;      // 0..3 (32 rows each)
    const int warpN = wid & 1;       // 0..1 (32 cols each)

    float acc[2][4][4];
    #pragma unroll
    for (int mi = 0; mi < 2; mi++)
        #pragma unroll
        for (int ni = 0; ni < 4; ni++)
            #pragma unroll
            for (int j = 0; j < 4; j++) acc[mi][ni][j] = 0.f;

    const int a_row_in_warp = lane & 15;
    const int a_khalf = (lane >> 4) & 1;
    const int b_row_in_tile = lane & 7;
    const int b_khalf = (lane >> 3) & 1;

    issue_chunk(A, Bt, sb, row0, col0, 0, 0, tid);

    for (int i = 0; i < CHUNKS; i++) {
        const int cur = i & 1;
        __syncthreads();   // all warps done with buffer cur^1 (chunk i-1)
        if (i + 1 < CHUNKS) {
            issue_chunk(A, Bt, sb, row0, col0, i + 1, cur ^ 1, tid);
            cp_wait1();    // chunk i complete (chunk i+1 still in flight)
        } else {
            cp_wait0();
        }
        __syncthreads();   // chunk i visible to all warps

        const uint32_t aoff = cur * STAGE_BYTES;
        const uint32_t boff = aoff + 16384u;
        #pragma unroll
        for (int kk = 0; kk < 4; kk++) {
            uint32_t afrag[2][4], bfrag[4][2];
            #pragma unroll
            for (int mi = 0; mi < 2; mi++) {
                const int r = warpM * 32 + mi * 16 + a_row_in_warp;
                ldm_x4(afrag[mi], sb + aoff + sw128((uint32_t)(r * 128 + kk * 32 + a_khalf * 16)));
            }
            #pragma unroll
            for (int ni = 0; ni < 4; ni++) {
                const int r = warpN * 32 + ni * 8 + b_row_in_tile;
                ldm_x2(bfrag[ni], sb + boff + sw128((uint32_t)(r * 128 + kk * 32 + b_khalf * 16)));
            }
            #pragma unroll
            for (int mi = 0; mi < 2; mi++)
                #pragma unroll
                for (int ni = 0; ni < 4; ni++)
                    mma_f16(acc[mi][ni], afrag[mi], bfrag[ni]);
        }
    }

    const int erow = lane >> 2;
    const int ecol = 2 * (lane & 3);
    #pragma unroll
    for (int mi = 0; mi < 2; mi++) {
        #pragma unroll
        for (int ni = 0; ni < 4; ni++) {
            const int r = row0 + warpM * 32 + mi * 16 + erow;
            const int c = col0 + warpN * 32 + ni * 8 + ecol;
            if (HOUT) {
                __half* C = (__half*)Cp;
                *(__half2*)(C + (size_t)r * DMODEL + c) =
                    __floats2half2_rn(acc[mi][ni][0], acc[mi][ni][1]);
                *(__half2*)(C + (size_t)(r + 8) * DMODEL + c) =
                    __floats2half2_rn(acc[mi][ni][2], acc[mi][ni][3]);
            } else {
                float* C = (float*)Cp;
                *(float2*)(C + (size_t)r * DMODEL + c) = make_float2(acc[mi][ni][0], acc[mi][ni][1]);
                *(float2*)(C + (size_t)(r + 8) * DMODEL + c) = make_float2(acc[mi][ni][2], acc[mi][ni][3]);
            }
        }
    }
}

// Fused Q/K/V projection: 512 + 128 + 128 tiles of 128x64
__global__ __launch_bounds__(256, 3) void gemm_qkv(const __half* __restrict__ Aq,
                                                   const __half* __restrict__ Ak,
                                                   const __half* __restrict__ Av,
                                                   const __half* __restrict__ Wb,
                                                   __half* __restrict__ Cq,
                                                   __half* __restrict__ Ck,
                                                   __half* __restrict__ Cv) {
    extern __shared__ __align__(1024) char smem[];
    int t = blockIdx.x;
    const __half *A, *B;
    __half* C;
    if (t < 512) { A = Aq; B = Wb; C = Cq; }
    else if (t < 640) { t -= 512; A = Ak; B = Wb + WSTRIDE; C = Ck; }
    else { t -= 640; A = Av; B = Wb + 2 * WSTRIDE; C = Cv; }
    gemm_tile<true>(A, B, C, (t >> 3) * 128, (t & 7) * 64, smem_u32(smem), threadIdx.x);
}

__global__ __launch_bounds__(256, 3) void gemm_one(const __half* __restrict__ A,
                                                   const __half* __restrict__ Bt,
                                                   float* __restrict__ C) {
    extern __shared__ __align__(1024) char smem[];
    gemm_tile<false>(A, Bt, C, blockIdx.y * 128, blockIdx.x * 64, smem_u32(smem), threadIdx.x);
}

// ---------------------------------------------------------------------------
// prep_all: fused activation fp16 conversion + weight transpose/convert.
// ---------------------------------------------------------------------------
struct __align__(8) hf4 { __half a, b, c, d; };

__global__ __launch_bounds__(256) void prep_all(const float4* __restrict__ q,
                                                const float4* __restrict__ k,
                                                const float4* __restrict__ v,
                                                const float* __restrict__ W0,
                                                const float* __restrict__ W1,
                                                const float* __restrict__ W2,
                                                const float* __restrict__ W3,
                                                __half* __restrict__ outq,
                                                __half* __restrict__ outk,
                                                __half* __restrict__ outv,
                                                __half* __restrict__ Wb,
                                                int Mq, int Mkv) {
    __shared__ float tbuf[32][33];
    const int nq = Mq * 128, nkv = Mkv * 128;
    const int nact = (nq + 2 * nkv + 255) / 256;
    const int tid = threadIdx.x;

    if ((int)blockIdx.x < nact) {
        const int gid = blockIdx.x * 256 + tid;
        const float4* src;
        __half* out;
        int loc;
        if (gid < nq) { src = q; out = outq; loc = gid; }
        else if (gid < nq + nkv) { src = k; out = outk; loc = gid - nq; }
        else if (gid < nq + 2 * nkv) { src = v; out = outv; loc = gid - nq - nkv; }
        else return;
        float4 x = src[loc];
        hf4 hv;
        hv.a = __float2half(x.x); hv.b = __float2half(x.y);
        hv.c = __float2half(x.z); hv.d = __float2half(x.w);
        *(hf4*)(out + (size_t)loc * 4) = hv;
    } else {
        int t = blockIdx.x - nact;          // 0..1023
        const int z = t >> 8;
        const int tt = t & 255;
        const int k0 = (tt >> 4) * 32, n0 = (tt & 15) * 32;
        const float* W = (z == 0) ? W0 : (z == 1) ? W1 : (z == 2) ? W2 : W3;
        __half* outW = Wb + (size_t)z * WSTRIDE;
        const int r0 = tid >> 5, cc = tid & 31;
        #pragma unroll
        for (int j = 0; j < 4; j++)
            tbuf[r0 + j * 8][cc] = W[(size_t)(k0 + r0 + j * 8) * DMODEL + n0 + cc];
        __syncthreads();
        #pragma unroll
        for (int j = 0; j < 4; j++)
            outW[(size_t)(n0 + r0 + j * 8) * GK + k0 + cc] = __float2half(tbuf[cc][r0 + j * 8]);
    }
}

// ---------------------------------------------------------------------------
// Sparse attention v5 (unchanged): all-fp16 I/O.
// ---------------------------------------------------------------------------
#define QBLK 64
#define CTILE 32
#define KSTRIDE 36

__device__ __forceinline__ int floordiv_s(int a, int d) {
    return (a >= 0) ? (a / d) : -((-a + d - 1) / d);
}

__global__ __launch_bounds__(256) void sparse_attn_v5(const __half* __restrict__ Qh,
                                                      const __half* __restrict__ Kh,
                                                      const __half* __restrict__ Vh,
                                                      __half* __restrict__ ctxh,
                                                      int Lq, int Lkv) {
    __shared__ __align__(16) __half2 Ksh[CTILE][KSTRIDE];
    __shared__ __align__(16) __half2 Vsh[CTILE][32];

    const int bh = blockIdx.y;
    const int b = bh / HEAD_NUM;
    const int h = bh % HEAD_NUM;
    const int c0 = blockIdx.x * QBLK;
    const int tid = threadIdx.x;
    const int wid = tid >> 5, lane = tid & 31;
    const int rlane = lane & 15;
    const int half = lane >> 4;

    const int colT0 = max(0, c0 / STRIDE - (R_SPAN - 1));

    {
        const int col = tid >> 3, d8 = tid & 7;
        if (colT0 + col < Lkv) {
            const uint4 kv = __ldg((const uint4*)(Kh + ((size_t)(b * Lkv + colT0 + col) * DMODEL) + h * 64 + d8 * 8));
            *(uint4*)&Ksh[col][d8 * 4] = kv;
        }
    }
    {
        const int col = tid >> 3, l8 = tid & 7;
        if (colT0 + col < Lkv) {
            const uint4 vv = __ldg((const uint4*)(Vh + ((size_t)(b * Lkv + colT0 + col) * DMODEL) + h * 64 + l8 * 8));
            *(uint4*)&Vsh[col][l8 * 4] = vv;
        }
    }
    __syncthreads();

    #pragma unroll
    for (int step = 0; step < 4; step++) {
        const int cbase = c0 + wid * 8 + step * 2;
        const int c = cbase + half;

        const int fd = floordiv_s(SPAN - 1 - c, STRIDE);
        const int col = rlane - fd;
        const int row = c - STRIDE * col;
        const bool valid = (row >= 0) && (row < SPAN) && (col >= 0) && (col < Lkv);
        const int ii = min(max(col - colT0, 0), CTILE - 1);

        const uint4* Qrow = (const uint4*)(Qh + ((size_t)(b * Lq + c) * DMODEL) + h * 64);
        float acc = 0.f;
        #pragma unroll
        for (int j8 = 0; j8 < 8; j8++) {
            const uint4 qp = __ldg(Qrow + j8);
            const uint4 kp = *(const uint4*)&Ksh[ii][j8 * 4];
            const float2 q0 = __half22float2(*(const __half2*)&qp.x);
            const float2 q1 = __half22float2(*(const __half2*)&qp.y);
            const float2 q2 = __half22float2(*(const __half2*)&qp.z);
            const float2 q3 = __half22float2(*(const __half2*)&qp.w);
            const float2 k0 = __half22float2(*(const __half2*)&kp.x);
            const float2 k1 = __half22float2(*(const __half2*)&kp.y);
            const float2 k2 = __half22float2(*(const __half2*)&kp.z);
            const float2 k3 = __half22float2(*(const __half2*)&kp.w);
            acc += q0.x * k0.x + q0.y * k0.y + q1.x * k1.x + q1.y * k1.y;
            acc += q2.x * k2.x + q2.y * k2.y + q3.x * k3.x + q3.y * k3.y;
        }
        const float sc = valid ? acc * 0.125f : -1e30f;

        float m = sc;
        #pragma unroll
        for (int off = 8; off > 0; off >>= 1)
            m = fmaxf(m, __shfl_xor_sync(0xffffffffu, m, off));
        const float e = valid ? __expf(sc - m) : 0.f;
        float s = e;
        #pragma unroll
        for (int off = 8; off > 0; off >>= 1)
            s += __shfl_xor_sync(0xffffffffu, s, off);
        const float w = e / s;

        #pragma unroll
        for (int qh = 0; qh < 2; qh++) {
            const int cq = cbase + qh;
            const int fdq = floordiv_s(SPAN - 1 - cq, STRIDE);
            float ox = 0.f, oy = 0.f;
            #pragma unroll
            for (int r = 0; r < R_SPAN; r++) {
                const float wr = __shfl_sync(0xffffffffu, w, qh * 16 + r);
                const int iir = min(max(r - fdq - colT0, 0), CTILE - 1);
                const float2 vv = __half22float2(Vsh[iir][lane]);
                ox += wr * vv.x;
                oy += wr * vv.y;
            }
            __half2 hp;
            hp.x = __float2half(ox);
            hp.y = __float2half(oy);
            *(__half2*)(ctxh + (size_t)(b * Lq + cq) * GK + h * DIM_V + 2 * lane) = hp;
        }
    }
}

// ---------------------------------------------------------------------------
// Launch
// ---------------------------------------------------------------------------
extern "C" void kernel_launch(void* const* d_in, const int* in_sizes, int n_in,
                              void* d_out, int out_size) {
    const float* q    = (const float*)d_in[0];
    const float* k    = (const float*)d_in[1];
    const float* v    = (const float*)d_in[2];
    const float* Wq   = (const float*)d_in[3];
    const float* Wk   = (const float*)d_in[4];
    const float* Wv   = (const float*)d_in[5];
    const float* Wout = (const float*)d_in[6];
    float* out = (float*)d_out;

    const int Lq  = in_sizes[0] / (BATCH * DMODEL);   // 4096
    const int Lkv = in_sizes[1] / (BATCH * DMODEL);   // 1024
    const int Mq  = BATCH * Lq;    // 8192
    const int Mkv = BATCH * Lkv;   // 2048

    __half *gAb, *gKb, *gVb, *gWb, *gQh, *gKh, *gVh;
    cudaGetSymbolAddress((void**)&gAb, g_Ab);
    cudaGetSymbolAddress((void**)&gKb, g_Kb);
    cudaGetSymbolAddress((void**)&gVb, g_Vb);
    cudaGetSymbolAddress((void**)&gWb, g_Wb4);
    cudaGetSymbolAddress((void**)&gQh, g_Qh);
    cudaGetSymbolAddress((void**)&gKh, g_Kh);
    cudaGetSymbolAddress((void**)&gVh, g_Vh);

    cudaFuncSetAttribute(gemm_qkv, cudaFuncAttributeMaxDynamicSharedMemorySize, GEMM_SMEM);
    cudaFuncSetAttribute(gemm_one, cudaFuncAttributeMaxDynamicSharedMemorySize, GEMM_SMEM);

    // 1. fused conversions
    const int nact = ((Mq + 2 * Mkv) * 128 + 255) / 256;
    prep_all<<<nact + 1024, 256>>>((const float4*)q, (const float4*)k, (const float4*)v,
                                   Wq, Wk, Wv, Wout, gAb, gKb, gVb, gWb, Mq, Mkv);

    // 2. fused Q/K/V projection GEMM (128x64 tiles: 512 + 128 + 128)
    gemm_qkv<<<768, 256, GEMM_SMEM>>>(gAb, gKb, gVb, gWb, gQh, gKh, gVh);

    // 3. sparse attention
    sparse_attn_v5<<<dim3(Lq / QBLK, BATCH * HEAD_NUM), 256>>>(gQh, gKh, gVh, gAb, Lq, Lkv);

    // 4. out projection -> fp32 d_out
    gemm_one<<<dim3(8, Mq / 128), 256, GEMM_SMEM>>>(gAb, gWb + 3 * (size_t)WSTRIDE, out);
}

// round 15
// speedup vs baseline: 1.0059x; 1.0059x over previous
#include <cuda_runtime.h>
#include <cuda_fp16.h>
#include <cstdint>

#define HEAD_NUM 8
#define DIM_QK 64
#define DIM_V 64
#define SPAN 64
#define STRIDE 4
#define R_SPAN 16

#define BATCH 2
#define MAX_LQ 4096
#define MAX_LKV 1024
#define DMODEL 512
#define GK 512           // single-rounded fp16 GEMM
#define CHUNKS 8         // GK / 64
#define WSTRIDE (DMODEL * GK)

#define NSM 148
#define GEMM_GRID (2 * NSM)   // persistent: 2 CTAs per SM

// ---------------------------------------------------------------------------
// Scratch (no cudaMalloc allowed)
// ---------------------------------------------------------------------------
__device__ __align__(16) __half g_Ab[BATCH * MAX_LQ * GK];    // q-act fp16, then ctx fp16
__device__ __align__(16) __half g_Kb[BATCH * MAX_LKV * GK];   // k-act fp16
__device__ __align__(16) __half g_Vb[BATCH * MAX_LKV * GK];   // v-act fp16
__device__ __align__(16) __half g_Wb4[4 * WSTRIDE];           // 4 weights (transposed) fp16
__device__ __align__(16) __half g_Qh[BATCH * MAX_LQ * DMODEL];
__device__ __align__(16) __half g_Kh[BATCH * MAX_LKV * DMODEL];
__device__ __align__(16) __half g_Vh[BATCH * MAX_LKV * DMODEL];

// ---------------------------------------------------------------------------
// Baseline-target PTX helpers
// ---------------------------------------------------------------------------
__device__ __forceinline__ uint32_t smem_u32(const void* p) {
    uint32_t a;
    asm("{ .reg .u64 t; cvta.to.shared.u64 t, %1; cvt.u32.u64 %0, t; }" : "=r"(a) : "l"(p));
    return a;
}
__device__ __forceinline__ void cp_async16(uint32_t saddr, const void* gaddr) {
    asm volatile("cp.async.cg.shared.global [%0], [%1], 16;" :: "r"(saddr), "l"(gaddr));
}
__device__ __forceinline__ void cp_commit() { asm volatile("cp.async.commit_group;" ::: "memory"); }
__device__ __forceinline__ void cp_wait1() { asm volatile("cp.async.wait_group 1;" ::: "memory"); }
__device__ __forceinline__ void cp_wait0() { asm volatile("cp.async.wait_group 0;" ::: "memory"); }
__device__ __forceinline__ void ldm_x4(uint32_t* r, uint32_t addr) {
    asm volatile("ldmatrix.sync.aligned.m8n8.x4.shared.b16 {%0,%1,%2,%3}, [%4];"
                 : "=r"(r[0]), "=r"(r[1]), "=r"(r[2]), "=r"(r[3]) : "r"(addr));
}
__device__ __forceinline__ void ldm_x2(uint32_t* r, uint32_t addr) {
    asm volatile("ldmatrix.sync.aligned.m8n8.x2.shared.b16 {%0,%1}, [%2];"
                 : "=r"(r[0]), "=r"(r[1]) : "r"(addr));
}
__device__ __forceinline__ void mma_f16(float* c, const uint32_t* a, const uint32_t* b) {
    asm volatile("mma.sync.aligned.m16n8k16.row.col.f32.f16.f16.f32 "
                 "{%0,%1,%2,%3}, {%4,%5,%6,%7}, {%8,%9}, {%0,%1,%2,%3};"
                 : "+f"(c[0]), "+f"(c[1]), "+f"(c[2]), "+f"(c[3])
                 : "r"(a[0]), "r"(a[1]), "r"(a[2]), "r"(a[3]), "r"(b[0]), "r"(b[1]));
}
__device__ __forceinline__ uint32_t sw128(uint32_t off) { return off ^ ((off >> 3) & 0x70); }

// ---------------------------------------------------------------------------
// GEMM tile worker (R13 config): CTA 128x64, 8 warps (4x2), warp tile 32x32.
// 3-stage cp.async pipeline. Stage = 24KB; total 72KB; 2 CTAs/SM.
// Entry __syncthreads protects stage reuse across persistent-tile iterations.
// ---------------------------------------------------------------------------
#define STAGE_BYTES 24576u
#define GEMM_SMEM (3 * STAGE_BYTES)

__device__ __forceinline__ void issue_chunk(const __half* __restrict__ A,
                                            const __half* __restrict__ Bt,
                                            uint32_t sb, int row0, int col0,
                                            int chunk, int stage, int tid) {
    const int k0 = chunk * 64;
    const uint32_t aoff = stage * STAGE_BYTES;
    const uint32_t boff = aoff + 16384u;
    #pragma unroll
    for (int p = 0; p < 4; p++) {
        const int idx = tid + p * 256;        // A: 128 rows x 8 x 16B
        const int r = idx >> 3;
        const int c8 = idx & 7;
        const uint32_t sw = sw128((uint32_t)(r * 128 + c8 * 16));
        cp_async16(sb + aoff + sw, A + (size_t)(row0 + r) * GK + k0 + c8 * 8);
    }
    #pragma unroll
    for (int p = 0; p < 2; p++) {
        const int idx = tid + p * 256;        // B: 64 rows x 8 x 16B
        const int r = idx >> 3;
        const int c8 = idx & 7;
        const uint32_t sw = sw128((uint32_t)(r * 128 + c8 * 16));
        cp_async16(sb + boff + sw, Bt + (size_t)(col0 + r) * GK + k0 + c8 * 8);
    }
    cp_commit();
}

template <bool HOUT>
__device__ __forceinline__ void gemm_tile(const __half* __restrict__ A,
                                          const __half* __restrict__ Bt,
                                          void* __restrict__ Cp,
                                          int row0, int col0, uint32_t sb, int tid) {
    const int wid = tid >> 5, lane = tid & 31;
    const int warpM = wid >> 1;      // 0..3 (32 rows each)
    const int warpN = wid & 1;       // 0..1 (32 cols each)

    __syncthreads();   // prior tile's consumers done before stage reuse

    float acc[2][4][4];
    #pragma unroll
    for (int mi = 0; mi < 2; mi++)
        #pragma unroll
        for (int ni = 0; ni < 4; ni++)
            #pragma unroll
            for (int j = 0; j < 4; j++) acc[mi][ni][j] = 0.f;

    const int a_row_in_warp = lane & 15;
    const int a_khalf = (lane >> 4) & 1;
    const int b_row_in_tile = lane & 7;
    const int b_khalf = (lane >> 3) & 1;

    issue_chunk(A, Bt, sb, row0, col0, 0, 0, tid);
    issue_chunk(A, Bt, sb, row0, col0, 1, 1, tid);

    int stage = 0, nstage = 2;
    for (int i = 0; i < CHUNKS; i++) {
        if (i + 1 < CHUNKS) cp_wait1(); else cp_wait0();
        __syncthreads();

        if (i + 2 < CHUNKS) {
            issue_chunk(A, Bt, sb, row0, col0, i + 2, nstage, tid);
            nstage = (nstage + 1 == 3) ? 0 : nstage + 1;
        }

        const uint32_t aoff = stage * STAGE_BYTES;
        const uint32_t boff = aoff + 16384u;
        #pragma unroll
        for (int kk = 0; kk < 4; kk++) {
            uint32_t afrag[2][4], bfrag[4][2];
            #pragma unroll
            for (int mi = 0; mi < 2; mi++) {
                const int r = warpM * 32 + mi * 16 + a_row_in_warp;
                ldm_x4(afrag[mi], sb + aoff + sw128((uint32_t)(r * 128 + kk * 32 + a_khalf * 16)));
            }
            #pragma unroll
            for (int ni = 0; ni < 4; ni++) {
                const int r = warpN * 32 + ni * 8 + b_row_in_tile;
                ldm_x2(bfrag[ni], sb + boff + sw128((uint32_t)(r * 128 + kk * 32 + b_khalf * 16)));
            }
            #pragma unroll
            for (int mi = 0; mi < 2; mi++)
                #pragma unroll
                for (int ni = 0; ni < 4; ni++)
                    mma_f16(acc[mi][ni], afrag[mi], bfrag[ni]);
        }
        stage = (stage + 1 == 3) ? 0 : stage + 1;
    }

    const int erow = lane >> 2;
    const int ecol = 2 * (lane & 3);
    #pragma unroll
    for (int mi = 0; mi < 2; mi++) {
        #pragma unroll
        for (int ni = 0; ni < 4; ni++) {
            const int r = row0 + warpM * 32 + mi * 16 + erow;
            const int c = col0 + warpN * 32 + ni * 8 + ecol;
            if (HOUT) {
                __half* C = (__half*)Cp;
                *(__half2*)(C + (size_t)r * DMODEL + c) =
                    __floats2half2_rn(acc[mi][ni][0], acc[mi][ni][1]);
                *(__half2*)(C + (size_t)(r + 8) * DMODEL + c) =
                    __floats2half2_rn(acc[mi][ni][2], acc[mi][ni][3]);
            } else {
                float* C = (float*)Cp;
                *(float2*)(C + (size_t)r * DMODEL + c) = make_float2(acc[mi][ni][0], acc[mi][ni][1]);
                *(float2*)(C + (size_t)(r + 8) * DMODEL + c) = make_float2(acc[mi][ni][2], acc[mi][ni][3]);
            }
        }
    }
}

// Persistent fused Q/K/V projection: 768 tiles of 128x64 over 296 CTAs
__global__ __launch_bounds__(256, 2) void gemm_qkv(const __half* __restrict__ Aq,
                                                   const __half* __restrict__ Ak,
                                                   const __half* __restrict__ Av,
                                                   const __half* __restrict__ Wb,
                                                   __half* __restrict__ Cq,
                                                   __half* __restrict__ Ck,
                                                   __half* __restrict__ Cv) {
    extern __shared__ __align__(1024) char smem[];
    const uint32_t sb = smem_u32(smem);
    for (int t0 = blockIdx.x; t0 < 768; t0 += GEMM_GRID) {
        int t = t0;
        const __half *A, *B;
        __half* C;
        if (t < 512) { A = Aq; B = Wb; C = Cq; }
        else if (t < 640) { t -= 512; A = Ak; B = Wb + WSTRIDE; C = Ck; }
        else { t -= 640; A = Av; B = Wb + 2 * WSTRIDE; C = Cv; }
        gemm_tile<true>(A, B, C, (t >> 3) * 128, (t & 7) * 64, sb, threadIdx.x);
    }
}

// Persistent out-projection: 512 tiles of 128x64 over 296 CTAs
__global__ __launch_bounds__(256, 2) void gemm_one(const __half* __restrict__ A,
                                                   const __half* __restrict__ Bt,
                                                   float* __restrict__ C) {
    extern __shared__ __align__(1024) char smem[];
    const uint32_t sb = smem_u32(smem);
    for (int t = blockIdx.x; t < 512; t += GEMM_GRID) {
        gemm_tile<false>(A, Bt, C, (t >> 3) * 128, (t & 7) * 64, sb, threadIdx.x);
    }
}

// ---------------------------------------------------------------------------
// prep_all: fused activation fp16 conversion + weight transpose/convert.
// ---------------------------------------------------------------------------
struct __align__(8) hf4 { __half a, b, c, d; };

__global__ __launch_bounds__(256) void prep_all(const float4* __restrict__ q,
                                                const float4* __restrict__ k,
                                                const float4* __restrict__ v,
                                                const float* __restrict__ W0,
                                                const float* __restrict__ W1,
                                                const float* __restrict__ W2,
                                                const float* __restrict__ W3,
                                                __half* __restrict__ outq,
                                                __half* __restrict__ outk,
                                                __half* __restrict__ outv,
                                                __half* __restrict__ Wb,
                                                int Mq, int Mkv) {
    __shared__ float tbuf[32][33];
    const int nq = Mq * 128, nkv = Mkv * 128;
    const int nact = (nq + 2 * nkv + 255) / 256;
    const int tid = threadIdx.x;

    if ((int)blockIdx.x < nact) {
        const int gid = blockIdx.x * 256 + tid;
        const float4* src;
        __half* out;
        int loc;
        if (gid < nq) { src = q; out = outq; loc = gid; }
        else if (gid < nq + nkv) { src = k; out = outk; loc = gid - nq; }
        else if (gid < nq + 2 * nkv) { src = v; out = outv; loc = gid - nq - nkv; }
        else return;
        float4 x = src[loc];
        hf4 hv;
        hv.a = __float2half(x.x); hv.b = __float2half(x.y);
        hv.c = __float2half(x.z); hv.d = __float2half(x.w);
        *(hf4*)(out + (size_t)loc * 4) = hv;
    } else {
        int t = blockIdx.x - nact;          // 0..1023
        const int z = t >> 8;
        const int tt = t & 255;
        const int k0 = (tt >> 4) * 32, n0 = (tt & 15) * 32;
        const float* W = (z == 0) ? W0 : (z == 1) ? W1 : (z == 2) ? W2 : W3;
        __half* outW = Wb + (size_t)z * WSTRIDE;
        const int r0 = tid >> 5, cc = tid & 31;
        #pragma unroll
        for (int j = 0; j < 4; j++)
            tbuf[r0 + j * 8][cc] = W[(size_t)(k0 + r0 + j * 8) * DMODEL + n0 + cc];
        __syncthreads();
        #pragma unroll
        for (int j = 0; j < 4; j++)
            outW[(size_t)(n0 + r0 + j * 8) * GK + k0 + cc] = __float2half(tbuf[cc][r0 + j * 8]);
    }
}

// ---------------------------------------------------------------------------
// Sparse attention v5 (unchanged): all-fp16 I/O.
// ---------------------------------------------------------------------------
#define QBLK 64
#define CTILE 32
#define KSTRIDE 36

__device__ __forceinline__ int floordiv_s(int a, int d) {
    return (a >= 0) ? (a / d) : -((-a + d - 1) / d);
}

__global__ __launch_bounds__(256) void sparse_attn_v5(const __half* __restrict__ Qh,
                                                      const __half* __restrict__ Kh,
                                                      const __half* __restrict__ Vh,
                                                      __half* __restrict__ ctxh,
                                                      int Lq, int Lkv) {
    __shared__ __align__(16) __half2 Ksh[CTILE][KSTRIDE];
    __shared__ __align__(16) __half2 Vsh[CTILE][32];

    const int bh = blockIdx.y;
    const int b = bh / HEAD_NUM;
    const int h = bh % HEAD_NUM;
    const int c0 = blockIdx.x * QBLK;
    const int tid = threadIdx.x;
    const int wid = tid >> 5, lane = tid & 31;
    const int rlane = lane & 15;
    const int half = lane >> 4;

    const int colT0 = max(0, c0 / STRIDE - (R_SPAN - 1));

    {
        const int col = tid >> 3, d8 = tid & 7;
        if (colT0 + col < Lkv) {
            const uint4 kv = __ldg((const uint4*)(Kh + ((size_t)(b * Lkv + colT0 + col) * DMODEL) + h * 64 + d8 * 8));
            *(uint4*)&Ksh[col][d8 * 4] = kv;
        }
    }
    {
        const int col = tid >> 3, l8 = tid & 7;
        if (colT0 + col < Lkv) {
            const uint4 vv = __ldg((const uint4*)(Vh + ((size_t)(b * Lkv + colT0 + col) * DMODEL) + h * 64 + l8 * 8));
            *(uint4*)&Vsh[col][l8 * 4] = vv;
        }
    }
    __syncthreads();

    #pragma unroll
    for (int step = 0; step < 4; step++) {
        const int cbase = c0 + wid * 8 + step * 2;
        const int c = cbase + half;

        const int fd = floordiv_s(SPAN - 1 - c, STRIDE);
        const int col = rlane - fd;
        const int row = c - STRIDE * col;
        const bool valid = (row >= 0) && (row < SPAN) && (col >= 0) && (col < Lkv);
        const int ii = min(max(col - colT0, 0), CTILE - 1);

        const uint4* Qrow = (const uint4*)(Qh + ((size_t)(b * Lq + c) * DMODEL) + h * 64);
        float acc = 0.f;
        #pragma unroll
        for (int j8 = 0; j8 < 8; j8++) {
            const uint4 qp = __ldg(Qrow + j8);
            const uint4 kp = *(const uint4*)&Ksh[ii][j8 * 4];
            const float2 q0 = __half22float2(*(const __half2*)&qp.x);
            const float2 q1 = __half22float2(*(const __half2*)&qp.y);
            const float2 q2 = __half22float2(*(const __half2*)&qp.z);
            const float2 q3 = __half22float2(*(const __half2*)&qp.w);
            const float2 k0 = __half22float2(*(const __half2*)&kp.x);
            const float2 k1 = __half22float2(*(const __half2*)&kp.y);
            const float2 k2 = __half22float2(*(const __half2*)&kp.z);
            const float2 k3 = __half22float2(*(const __half2*)&kp.w);
            acc += q0.x * k0.x + q0.y * k0.y + q1.x * k1.x + q1.y * k1.y;
            acc += q2.x * k2.x + q2.y * k2.y + q3.x * k3.x + q3.y * k3.y;
        }
        const float sc = valid ? acc * 0.125f : -1e30f;

        float m = sc;
        #pragma unroll
        for (int off = 8; off > 0; off >>= 1)
            m = fmaxf(m, __shfl_xor_sync(0xffffffffu, m, off));
        const float e = valid ? __expf(sc - m) : 0.f;
        float s = e;
        #pragma unroll
        for (int off = 8; off > 0; off >>= 1)
            s += __shfl_xor_sync(0xffffffffu, s, off);
        const float w = e / s;

        #pragma unroll
        for (int qh = 0; qh < 2; qh++) {
            const int cq = cbase + qh;
            const int fdq = floordiv_s(SPAN - 1 - cq, STRIDE);
            float ox = 0.f, oy = 0.f;
            #pragma unroll
            for (int r = 0; r < R_SPAN; r++) {
                const float wr = __shfl_sync(0xffffffffu, w, qh * 16 + r);
                const int iir = min(max(r - fdq - colT0, 0), CTILE - 1);
                const float2 vv = __half22float2(Vsh[iir][lane]);
                ox += wr * vv.x;
                oy += wr * vv.y;
            }
            __half2 hp;
            hp.x = __float2half(ox);
            hp.y = __float2half(oy);
            *(__half2*)(ctxh + (size_t)(b * Lq + cq) * GK + h * DIM_V + 2 * lane) = hp;
        }
    }
}

// ---------------------------------------------------------------------------
// Launch
// ---------------------------------------------------------------------------
extern "C" void kernel_launch(void* const* d_in, const int* in_sizes, int n_in,
                              void* d_out, int out_size) {
    const float* q    = (const float*)d_in[0];
    const float* k    = (const float*)d_in[1];
    const float* v    = (const float*)d_in[2];
    const float* Wq   = (const float*)d_in[3];
    const float* Wk   = (const float*)d_in[4];
    const float* Wv   = (const float*)d_in[5];
    const float* Wout = (const float*)d_in[6];
    float* out = (float*)d_out;

    const int Lq  = in_sizes[0] / (BATCH * DMODEL);   // 4096
    const int Lkv = in_sizes[1] / (BATCH * DMODEL);   // 1024
    const int Mq  = BATCH * Lq;    // 8192
    const int Mkv = BATCH * Lkv;   // 2048

    __half *gAb, *gKb, *gVb, *gWb, *gQh, *gKh, *gVh;
    cudaGetSymbolAddress((void**)&gAb, g_Ab);
    cudaGetSymbolAddress((void**)&gKb, g_Kb);
    cudaGetSymbolAddress((void**)&gVb, g_Vb);
    cudaGetSymbolAddress((void**)&gWb, g_Wb4);
    cudaGetSymbolAddress((void**)&gQh, g_Qh);
    cudaGetSymbolAddress((void**)&gKh, g_Kh);
    cudaGetSymbolAddress((void**)&gVh, g_Vh);

    cudaFuncSetAttribute(gemm_qkv, cudaFuncAttributeMaxDynamicSharedMemorySize, GEMM_SMEM);
    cudaFuncSetAttribute(gemm_one, cudaFuncAttributeMaxDynamicSharedMemorySize, GEMM_SMEM);

    // 1. fused conversions
    const int nact = ((Mq + 2 * Mkv) * 128 + 255) / 256;
    prep_all<<<nact + 1024, 256>>>((const float4*)q, (const float4*)k, (const float4*)v,
                                   Wq, Wk, Wv, Wout, gAb, gKb, gVb, gWb, Mq, Mkv);

    // 2. persistent fused Q/K/V projection GEMM
    gemm_qkv<<<GEMM_GRID, 256, GEMM_SMEM>>>(gAb, gKb, gVb, gWb, gQh, gKh, gVh);

    // 3. sparse attention
    sparse_attn_v5<<<dim3(Lq / QBLK, BATCH * HEAD_NUM), 256>>>(gQh, gKh, gVh, gAb, Lq, Lkv);

    // 4. persistent out projection -> fp32 d_out
    gemm_one<<<GEMM_GRID, 256, GEMM_SMEM>>>(gAb, gWb + 3 * (size_t)WSTRIDE, out);
}

// round 16
// speedup vs baseline: 1.0428x; 1.0367x over previous
#include <cuda_runtime.h>
#include <cuda_fp16.h>
#include <cstdint>

#define HEAD_NUM 8
#define DIM_QK 64
#define DIM_V 64
#define SPAN 64
#define STRIDE 4
#define R_SPAN 16

#define BATCH 2
#define MAX_LQ 4096
#define MAX_LKV 1024
#define DMODEL 512
#define GK 512           // single-rounded fp16 GEMM
#define CHUNKS 8         // GK / 64
#define WSTRIDE (DMODEL * GK)

// ---------------------------------------------------------------------------
// Scratch (no cudaMalloc allowed)
// ---------------------------------------------------------------------------
__device__ __align__(16) __half g_Ab[BATCH * MAX_LQ * GK];    // q-act fp16, then ctx fp16
__device__ __align__(16) __half g_Kb[BATCH * MAX_LKV * GK];   // k-act fp16
__device__ __align__(16) __half g_Vb[BATCH * MAX_LKV * GK];   // v-act fp16
__device__ __align__(16) __half g_Wb4[4 * WSTRIDE];           // 4 weights (transposed) fp16
__device__ __align__(16) __half g_Qh[BATCH * MAX_LQ * DMODEL];
__device__ __align__(16) __half g_Kh[BATCH * MAX_LKV * DMODEL];
__device__ __align__(16) __half g_Vh[BATCH * MAX_LKV * DMODEL];

// ---------------------------------------------------------------------------
// Baseline-target PTX helpers
// ---------------------------------------------------------------------------
__device__ __forceinline__ uint32_t smem_u32(const void* p) {
    uint32_t a;
    asm("{ .reg .u64 t; cvta.to.shared.u64 t, %1; cvt.u32.u64 %0, t; }" : "=r"(a) : "l"(p));
    return a;
}
__device__ __forceinline__ void cp_async16(uint32_t saddr, const void* gaddr) {
    asm volatile("cp.async.cg.shared.global [%0], [%1], 16;" :: "r"(saddr), "l"(gaddr));
}
__device__ __forceinline__ void cp_commit() { asm volatile("cp.async.commit_group;" ::: "memory"); }
__device__ __forceinline__ void cp_wait1() { asm volatile("cp.async.wait_group 1;" ::: "memory"); }
__device__ __forceinline__ void cp_wait0() { asm volatile("cp.async.wait_group 0;" ::: "memory"); }
__device__ __forceinline__ void ldm_x4(uint32_t* r, uint32_t addr) {
    asm volatile("ldmatrix.sync.aligned.m8n8.x4.shared.b16 {%0,%1,%2,%3}, [%4];"
                 : "=r"(r[0]), "=r"(r[1]), "=r"(r[2]), "=r"(r[3]) : "r"(addr));
}
__device__ __forceinline__ void ldm_x2(uint32_t* r, uint32_t addr) {
    asm volatile("ldmatrix.sync.aligned.m8n8.x2.shared.b16 {%0,%1}, [%2];"
                 : "=r"(r[0]), "=r"(r[1]) : "r"(addr));
}
__device__ __forceinline__ void mma_f16(float* c, const uint32_t* a, const uint32_t* b) {
    asm volatile("mma.sync.aligned.m16n8k16.row.col.f32.f16.f16.f32 "
                 "{%0,%1,%2,%3}, {%4,%5,%6,%7}, {%8,%9}, {%0,%1,%2,%3};"
                 : "+f"(c[0]), "+f"(c[1]), "+f"(c[2]), "+f"(c[3])
                 : "r"(a[0]), "r"(a[1]), "r"(a[2]), "r"(a[3]), "r"(b[0]), "r"(b[1]));
}
__device__ __forceinline__ uint32_t sw128(uint32_t off) { return off ^ ((off >> 3) & 0x70); }

// ---------------------------------------------------------------------------
// GEMM tile worker (R13 config — best known): CTA 128x64, 8 warps (4x2),
// warp tile 32x32, 3-stage cp.async pipeline. Stage = 24KB; total 72KB;
// launch_bounds(256, 2) -> 2 CTAs/SM.
// ---------------------------------------------------------------------------
#define STAGE_BYTES 24576u
#define GEMM_SMEM (3 * STAGE_BYTES)

__device__ __forceinline__ void issue_chunk(const __half* __restrict__ A,
                                            const __half* __restrict__ Bt,
                                            uint32_t sb, int row0, int col0,
                                            int chunk, int stage, int tid) {
    const int k0 = chunk * 64;
    const uint32_t aoff = stage * STAGE_BYTES;
    const uint32_t boff = aoff + 16384u;
    #pragma unroll
    for (int p = 0; p < 4; p++) {
        const int idx = tid + p * 256;        // A: 128 rows x 8 x 16B
        const int r = idx >> 3;
        const int c8 = idx & 7;
        const uint32_t sw = sw128((uint32_t)(r * 128 + c8 * 16));
        cp_async16(sb + aoff + sw, A + (size_t)(row0 + r) * GK + k0 + c8 * 8);
    }
    #pragma unroll
    for (int p = 0; p < 2; p++) {
        const int idx = tid + p * 256;        // B: 64 rows x 8 x 16B
        const int r = idx >> 3;
        const int c8 = idx & 7;
        const uint32_t sw = sw128((uint32_t)(r * 128 + c8 * 16));
        cp_async16(sb + boff + sw, Bt + (size_t)(col0 + r) * GK + k0 + c8 * 8);
    }
    cp_commit();
}

template <bool HOUT>
__device__ __forceinline__ void gemm_tile(const __half* __restrict__ A,
                                          const __half* __restrict__ Bt,
                                          void* __restrict__ Cp,
                                          int row0, int col0, uint32_t sb, int tid) {
    const int wid = tid >> 5, lane = tid & 31;
    const int warpM = wid >> 1;      // 0..3 (32 rows each)
    const int warpN = wid & 1;       // 0..1 (32 cols each)

    float acc[2][4][4];
    #pragma unroll
    for (int mi = 0; mi < 2; mi++)
        #pragma unroll
        for (int ni = 0; ni < 4; ni++)
            #pragma unroll
            for (int j = 0; j < 4; j++) acc[mi][ni][j] = 0.f;

    const int a_row_in_warp = lane & 15;
    const int a_khalf = (lane >> 4) & 1;
    const int b_row_in_tile = lane & 7;
    const int b_khalf = (lane >> 3) & 1;

    issue_chunk(A, Bt, sb, row0, col0, 0, 0, tid);
    issue_chunk(A, Bt, sb, row0, col0, 1, 1, tid);

    int stage = 0, nstage = 2;
    for (int i = 0; i < CHUNKS; i++) {
        if (i + 1 < CHUNKS) cp_wait1(); else cp_wait0();
        __syncthreads();

        if (i + 2 < CHUNKS) {
            issue_chunk(A, Bt, sb, row0, col0, i + 2, nstage, tid);
            nstage = (nstage + 1 == 3) ? 0 : nstage + 1;
        }

        const uint32_t aoff = stage * STAGE_BYTES;
        const uint32_t boff = aoff + 16384u;
        #pragma unroll
        for (int kk = 0; kk < 4; kk++) {
            uint32_t afrag[2][4], bfrag[4][2];
            #pragma unroll
            for (int mi = 0; mi < 2; mi++) {
                const int r = warpM * 32 + mi * 16 + a_row_in_warp;
                ldm_x4(afrag[mi], sb + aoff + sw128((uint32_t)(r * 128 + kk * 32 + a_khalf * 16)));
            }
            #pragma unroll
            for (int ni = 0; ni < 4; ni++) {
                const int r = warpN * 32 + ni * 8 + b_row_in_tile;
                ldm_x2(bfrag[ni], sb + boff + sw128((uint32_t)(r * 128 + kk * 32 + b_khalf * 16)));
            }
            #pragma unroll
            for (int mi = 0; mi < 2; mi++)
                #pragma unroll
                for (int ni = 0; ni < 4; ni++)
                    mma_f16(acc[mi][ni], afrag[mi], bfrag[ni]);
        }
        stage = (stage + 1 == 3) ? 0 : stage + 1;
    }

    const int erow = lane >> 2;
    const int ecol = 2 * (lane & 3);
    #pragma unroll
    for (int mi = 0; mi < 2; mi++) {
        #pragma unroll
        for (int ni = 0; ni < 4; ni++) {
            const int r = row0 + warpM * 32 + mi * 16 + erow;
            const int c = col0 + warpN * 32 + ni * 8 + ecol;
            if (HOUT) {
                __half* C = (__half*)Cp;
                *(__half2*)(C + (size_t)r * DMODEL + c) =
                    __floats2half2_rn(acc[mi][ni][0], acc[mi][ni][1]);
                *(__half2*)(C + (size_t)(r + 8) * DMODEL + c) =
                    __floats2half2_rn(acc[mi][ni][2], acc[mi][ni][3]);
            } else {
                float* C = (float*)Cp;
                *(float2*)(C + (size_t)r * DMODEL + c) = make_float2(acc[mi][ni][0], acc[mi][ni][1]);
                *(float2*)(C + (size_t)(r + 8) * DMODEL + c) = make_float2(acc[mi][ni][2], acc[mi][ni][3]);
            }
        }
    }
}

// Fused Q/K/V projection: 512 + 128 + 128 tiles of 128x64
__global__ __launch_bounds__(256, 2) void gemm_qkv(const __half* __restrict__ Aq,
                                                   const __half* __restrict__ Ak,
                                                   const __half* __restrict__ Av,
                                                   const __half* __restrict__ Wb,
                                                   __half* __restrict__ Cq,
                                                   __half* __restrict__ Ck,
                                                   __half* __restrict__ Cv) {
    extern __shared__ __align__(1024) char smem[];
    int t = blockIdx.x;
    const __half *A, *B;
    __half* C;
    if (t < 512) { A = Aq; B = Wb; C = Cq; }
    else if (t < 640) { t -= 512; A = Ak; B = Wb + WSTRIDE; C = Ck; }
    else { t -= 640; A = Av; B = Wb + 2 * WSTRIDE; C = Cv; }
    gemm_tile<true>(A, B, C, (t >> 3) * 128, (t & 7) * 64, smem_u32(smem), threadIdx.x);
}

__global__ __launch_bounds__(256, 2) void gemm_one(const __half* __restrict__ A,
                                                   const __half* __restrict__ Bt,
                                                   float* __restrict__ C) {
    extern __shared__ __align__(1024) char smem[];
    gemm_tile<false>(A, Bt, C, blockIdx.y * 128, blockIdx.x * 64, smem_u32(smem), threadIdx.x);
}

// ---------------------------------------------------------------------------
// prep_all: fused activation fp16 conversion (8 elems/thread, 16B stores)
// + weight transpose/convert.
// ---------------------------------------------------------------------------
__global__ __launch_bounds__(256) void prep_all(const float4* __restrict__ q,
                                                const float4* __restrict__ k,
                                                const float4* __restrict__ v,
                                                const float* __restrict__ W0,
                                                const float* __restrict__ W1,
                                                const float* __restrict__ W2,
                                                const float* __restrict__ W3,
                                                __half* __restrict__ outq,
                                                __half* __restrict__ outk,
                                                __half* __restrict__ outv,
                                                __half* __restrict__ Wb,
                                                int Mq, int Mkv) {
    __shared__ float tbuf[32][33];
    const int nq8 = Mq * 64, nkv8 = Mkv * 64;   // 8-element groups
    const int nact = (nq8 + 2 * nkv8 + 255) / 256;
    const int tid = threadIdx.x;

    if ((int)blockIdx.x < nact) {
        const int gid = blockIdx.x * 256 + tid;
        const float4* src;
        __half* out;
        int loc;
        if (gid < nq8) { src = q; out = outq; loc = gid; }
        else if (gid < nq8 + nkv8) { src = k; out = outk; loc = gid - nq8; }
        else if (gid < nq8 + 2 * nkv8) { src = v; out = outv; loc = gid - nq8 - nkv8; }
        else return;
        const float4 x0 = src[2 * loc];
        const float4 x1 = src[2 * loc + 1];
        __half2 h[4];
        h[0] = __floats2half2_rn(x0.x, x0.y);
        h[1] = __floats2half2_rn(x0.z, x0.w);
        h[2] = __floats2half2_rn(x1.x, x1.y);
        h[3] = __floats2half2_rn(x1.z, x1.w);
        *(uint4*)(out + (size_t)loc * 8) = *(const uint4*)h;
    } else {
        int t = blockIdx.x - nact;          // 0..1023
        const int z = t >> 8;
        const int tt = t & 255;
        const int k0 = (tt >> 4) * 32, n0 = (tt & 15) * 32;
        const float* W = (z == 0) ? W0 : (z == 1) ? W1 : (z == 2) ? W2 : W3;
        __half* outW = Wb + (size_t)z * WSTRIDE;
        const int r0 = tid >> 5, cc = tid & 31;
        #pragma unroll
        for (int j = 0; j < 4; j++)
            tbuf[r0 + j * 8][cc] = W[(size_t)(k0 + r0 + j * 8) * DMODEL + n0 + cc];
        __syncthreads();
        #pragma unroll
        for (int j = 0; j < 4; j++)
            outW[(size_t)(n0 + r0 + j * 8) * GK + k0 + cc] = __float2half(tbuf[cc][r0 + j * 8]);
    }
}

// ---------------------------------------------------------------------------
// Sparse attention v5 (unchanged): all-fp16 I/O.
// ---------------------------------------------------------------------------
#define QBLK 64
#define CTILE 32
#define KSTRIDE 36

__device__ __forceinline__ int floordiv_s(int a, int d) {
    return (a >= 0) ? (a / d) : -((-a + d - 1) / d);
}

__global__ __launch_bounds__(256) void sparse_attn_v5(const __half* __restrict__ Qh,
                                                      const __half* __restrict__ Kh,
                                                      const __half* __restrict__ Vh,
                                                      __half* __restrict__ ctxh,
                                                      int Lq, int Lkv) {
    __shared__ __align__(16) __half2 Ksh[CTILE][KSTRIDE];
    __shared__ __align__(16) __half2 Vsh[CTILE][32];

    const int bh = blockIdx.y;
    const int b = bh / HEAD_NUM;
    const int h = bh % HEAD_NUM;
    const int c0 = blockIdx.x * QBLK;
    const int tid = threadIdx.x;
    const int wid = tid >> 5, lane = tid & 31;
    const int rlane = lane & 15;
    const int half = lane >> 4;

    const int colT0 = max(0, c0 / STRIDE - (R_SPAN - 1));

    {
        const int col = tid >> 3, d8 = tid & 7;
        if (colT0 + col < Lkv) {
            const uint4 kv = __ldg((const uint4*)(Kh + ((size_t)(b * Lkv + colT0 + col) * DMODEL) + h * 64 + d8 * 8));
            *(uint4*)&Ksh[col][d8 * 4] = kv;
        }
    }
    {
        const int col = tid >> 3, l8 = tid & 7;
        if (colT0 + col < Lkv) {
            const uint4 vv = __ldg((const uint4*)(Vh + ((size_t)(b * Lkv + colT0 + col) * DMODEL) + h * 64 + l8 * 8));
            *(uint4*)&Vsh[col][l8 * 4] = vv;
        }
    }
    __syncthreads();

    #pragma unroll
    for (int step = 0; step < 4; step++) {
        const int cbase = c0 + wid * 8 + step * 2;
        const int c = cbase + half;

        const int fd = floordiv_s(SPAN - 1 - c, STRIDE);
        const int col = rlane - fd;
        const int row = c - STRIDE * col;
        const bool valid = (row >= 0) && (row < SPAN) && (col >= 0) && (col < Lkv);
        const int ii = min(max(col - colT0, 0), CTILE - 1);

        const uint4* Qrow = (const uint4*)(Qh + ((size_t)(b * Lq + c) * DMODEL) + h * 64);
        float acc = 0.f;
        #pragma unroll
        for (int j8 = 0; j8 < 8; j8++) {
            const uint4 qp = __ldg(Qrow + j8);
            const uint4 kp = *(const uint4*)&Ksh[ii][j8 * 4];
            const float2 q0 = __half22float2(*(const __half2*)&qp.x);
            const float2 q1 = __half22float2(*(const __half2*)&qp.y);
            const float2 q2 = __half22float2(*(const __half2*)&qp.z);
            const float2 q3 = __half22float2(*(const __half2*)&qp.w);
            const float2 k0 = __half22float2(*(const __half2*)&kp.x);
            const float2 k1 = __half22float2(*(const __half2*)&kp.y);
            const float2 k2 = __half22float2(*(const __half2*)&kp.z);
            const float2 k3 = __half22float2(*(const __half2*)&kp.w);
            acc += q0.x * k0.x + q0.y * k0.y + q1.x * k1.x + q1.y * k1.y;
            acc += q2.x * k2.x + q2.y * k2.y + q3.x * k3.x + q3.y * k3.y;
        }
        const float sc = valid ? acc * 0.125f : -1e30f;

        float m = sc;
        #pragma unroll
        for (int off = 8; off > 0; off >>= 1)
            m = fmaxf(m, __shfl_xor_sync(0xffffffffu, m, off));
        const float e = valid ? __expf(sc - m) : 0.f;
        float s = e;
        #pragma unroll
        for (int off = 8; off > 0; off >>= 1)
            s += __shfl_xor_sync(0xffffffffu, s, off);
        const float w = e / s;

        #pragma unroll
        for (int qh = 0; qh < 2; qh++) {
            const int cq = cbase + qh;
            const int fdq = floordiv_s(SPAN - 1 - cq, STRIDE);
            float ox = 0.f, oy = 0.f;
            #pragma unroll
            for (int r = 0; r < R_SPAN; r++) {
                const float wr = __shfl_sync(0xffffffffu, w, qh * 16 + r);
                const int iir = min(max(r - fdq - colT0, 0), CTILE - 1);
                const float2 vv = __half22float2(Vsh[iir][lane]);
                ox += wr * vv.x;
                oy += wr * vv.y;
            }
            __half2 hp;
            hp.x = __float2half(ox);
            hp.y = __float2half(oy);
            *(__half2*)(ctxh + (size_t)(b * Lq + cq) * GK + h * DIM_V + 2 * lane) = hp;
        }
    }
}

// ---------------------------------------------------------------------------
// Launch
// ---------------------------------------------------------------------------
extern "C" void kernel_launch(void* const* d_in, const int* in_sizes, int n_in,
                              void* d_out, int out_size) {
    const float* q    = (const float*)d_in[0];
    const float* k    = (const float*)d_in[1];
    const float* v    = (const float*)d_in[2];
    const float* Wq   = (const float*)d_in[3];
    const float* Wk   = (const float*)d_in[4];
    const float* Wv   = (const float*)d_in[5];
    const float* Wout = (const float*)d_in[6];
    float* out = (float*)d_out;

    const int Lq  = in_sizes[0] / (BATCH * DMODEL);   // 4096
    const int Lkv = in_sizes[1] / (BATCH * DMODEL);   // 1024
    const int Mq  = BATCH * Lq;    // 8192
    const int Mkv = BATCH * Lkv;   // 2048

    __half *gAb, *gKb, *gVb, *gWb, *gQh, *gKh, *gVh;
    cudaGetSymbolAddress((void**)&gAb, g_Ab);
    cudaGetSymbolAddress((void**)&gKb, g_Kb);
    cudaGetSymbolAddress((void**)&gVb, g_Vb);
    cudaGetSymbolAddress((void**)&gWb, g_Wb4);
    cudaGetSymbolAddress((void**)&gQh, g_Qh);
    cudaGetSymbolAddress((void**)&gKh, g_Kh);
    cudaGetSymbolAddress((void**)&gVh, g_Vh);

    cudaFuncSetAttribute(gemm_qkv, cudaFuncAttributeMaxDynamicSharedMemorySize, GEMM_SMEM);
    cudaFuncSetAttribute(gemm_one, cudaFuncAttributeMaxDynamicSharedMemorySize, GEMM_SMEM);

    // 1. fused conversions (act: 8 elems/thread)
    const int nact = ((Mq + 2 * Mkv) * 64 + 255) / 256;
    prep_all<<<nact + 1024, 256>>>((const float4*)q, (const float4*)k, (const float4*)v,
                                   Wq, Wk, Wv, Wout, gAb, gKb, gVb, gWb, Mq, Mkv);

    // 2. fused Q/K/V projection GEMM (128x64 tiles: 512 + 128 + 128)
    gemm_qkv<<<768, 256, GEMM_SMEM>>>(gAb, gKb, gVb, gWb, gQh, gKh, gVh);

    // 3. sparse attention
    sparse_attn_v5<<<dim3(Lq / QBLK, BATCH * HEAD_NUM), 256>>>(gQh, gKh, gVh, gAb, Lq, Lkv);

    // 4. out projection -> fp32 d_out
    gemm_one<<<dim3(8, Mq / 128), 256, GEMM_SMEM>>>(gAb, gWb + 3 * (size_t)WSTRIDE, out);
}